// round 17
// baseline (speedup 1.0000x reference)
#include <cuda_runtime.h>
#include <cuda_bf16.h>
#include <cstdint>

// BasisEncoder: out[b][q] = ((x[b] & 63) == q) ? 1.0f : 0.0f
// 256 MB pure store stream at the chip write-drain ceiling (~6.7 TB/s eff).
//
// Matrix results (ncu dur / DRAM-active):
//   STG.cs.v8              41.6us / 5.14 TB/s
//   STG default v8         56.9us / 3.72 TB/s
//   TMA 32KB default       40.2us / 5.29 TB/s
//   TMA 16KB default       40.4us / 5.26 TB/s
//   TMA 32KB evict_first   40.1us / 5.30 TB/s  <- best bench (39.4us)
// R17 = final combo: 16 KB tiles (2x resident blocks -> more concurrent
// drains, finer tail) + evict_first cache hint on the bulk store.

static __device__ __forceinline__ uint32_t smem_u32(const void* p) {
    uint32_t a;
    asm("{ .reg .u64 t; cvta.to.shared.u64 t, %1; cvt.u32.u64 %0, t; }"
        : "=r"(a) : "l"(p));
    return a;
}

__global__ void __launch_bounds__(256)
basis_encoder_kernel(const int* __restrict__ x,
                     float* __restrict__ out) {
    __shared__ __align__(128) float tile[64 * 64];     // 16 KB

    int t    = threadIdx.x;
    int row0 = blockIdx.x << 6;                        // 64 rows per block
    int qb   = (t & 15) << 2;                          // quad base col

    // Direct computed fill: 1024 float4 (64 rows x 16 quads), 4 per thread.
    float4* dst = reinterpret_cast<float4*>(tile);
#pragma unroll
    for (int k = 0; k < 4; k++) {
        int j   = t + k * 256;
        int row = j >> 4;
        int idx = __ldg(&x[row0 + row]) & 63;          // (x%256)%64 == x&63
        float4 v;
        v.x = (idx == qb + 0) ? 1.0f : 0.0f;
        v.y = (idx == qb + 1) ? 1.0f : 0.0f;
        v.z = (idx == qb + 2) ? 1.0f : 0.0f;
        v.w = (idx == qb + 3) ? 1.0f : 0.0f;
        dst[j] = v;
    }
    asm volatile("fence.proxy.async.shared::cta;" ::: "memory");
    __syncthreads();

    // One 16 KB bulk TMA store with an evict_first L2 policy.
    if (t == 0) {
        uint32_t s = smem_u32(tile);
        const float* g = out + ((size_t)row0 << 6);
        asm volatile(
            "{\n\t"
            ".reg .b64 pol;\n\t"
            "createpolicy.fractional.L2::evict_first.b64 pol, 1.0;\n\t"
            "cp.async.bulk.global.shared::cta.bulk_group.L2::cache_hint "
            "[%0], [%1], %2, pol;\n\t"
            "}"
            :: "l"(g), "r"(s), "n"(64 * 64 * 4)
            : "memory");
        asm volatile("cp.async.bulk.commit_group;" ::: "memory");
        asm volatile("cp.async.bulk.wait_group.read 0;" ::: "memory");
    }
}

extern "C" void kernel_launch(void* const* d_in, const int* in_sizes, int n_in,
                              void* d_out, int out_size) {
    const int* x   = (const int*)d_in[0];
    float*     out = (float*)d_out;

    int rows   = out_size >> 6;        // 1,048,576
    int blocks = rows >> 6;            // 16,384 blocks of 64 rows

    basis_encoder_kernel<<<blocks, 256>>>(x, out);
}